// round 3
// baseline (speedup 1.0000x reference)
#include <cuda_runtime.h>
#include <cstdint>

typedef unsigned long long ull;

// ---------------- problem constants ----------------
// T=4, B=2, Ck=256, Cv=512, H=W=96, scales {1,2,3,6}, MAX=6, M=144, N=9216

// ---------------- device scratch (static, no allocation) ----------------
__device__ __align__(16) float g_pool6_k[2048 * 36];          // [T*B*Ck][36] block means
__device__ __align__(16) float g_pool6_v[4096 * 36];          // [T*B*Cv][36]
__device__ __align__(16) float g_convk[4 * 2 * 4 * 64 * 36];  // [tb][si][o][pos<=36]
__device__ __align__(16) float g_convv[4 * 2 * 4 * 128 * 36];
__device__ __align__(16) float g_mkT[2 * 256 * 144];          // [b][c][m]  (x Ck^-0.5 folded)
__device__ __align__(16) float g_mvT[2 * 144 * 512];          // [b][m][v]

__constant__ int c_scale[4] = {1, 2, 3, 6};
// bilinear upsample tables (jax.image.resize bilinear, half-pixel, normalized == edge clamp)
__constant__ int UI0[4][6] = {
    {0,0,0,0,0,0},
    {0,0,0,0,1,1},
    {0,0,0,1,1,2},
    {0,1,2,3,4,5}};
__constant__ int UI1[4][6] = {
    {0,0,0,0,0,0},
    {0,1,1,1,1,1},
    {0,1,1,2,2,2},
    {0,1,2,3,4,5}};
__constant__ float UW[4][6] = {
    {0.f,0.f,0.f,0.f,0.f,0.f},
    {0.f, 1.f/6.f, 0.5f, 5.f/6.f, 0.f, 0.f},
    {0.f, 0.25f, 0.75f, 0.25f, 0.75f, 0.f},
    {0.f,0.f,0.f,0.f,0.f,0.f}};

// ---------------- f32x2 helpers ----------------
__device__ __forceinline__ ull fma2(ull a, ull b, ull c) {
    ull d;
    asm("fma.rn.f32x2 %0, %1, %2, %3;" : "=l"(d) : "l"(a), "l"(b), "l"(c));
    return d;
}
__device__ __forceinline__ ull dup2(float x) {
    ull d; unsigned u = __float_as_uint(x);
    asm("mov.b64 %0, {%1, %1};" : "=l"(d) : "r"(u));
    return d;
}
__device__ __forceinline__ ull pack2(float lo, float hi) {
    ull d; unsigned a = __float_as_uint(lo), b = __float_as_uint(hi);
    asm("mov.b64 %0, {%1, %2};" : "=l"(d) : "r"(a), "r"(b));
    return d;
}
__device__ __forceinline__ void unpack2(ull v, float& lo, float& hi) {
    unsigned a, b;
    asm("mov.b64 {%0, %1}, %2;" : "=r"(a), "=r"(b) : "l"(v));
    lo = __uint_as_float(a); hi = __uint_as_float(b);
}

// ================= K1: 16x16 block means (all scales derive from these) =================
__global__ void k_pool(const float* __restrict__ mk, const float* __restrict__ mv) {
    int p = blockIdx.x;
    const float* src; float* dst;
    if (p < 2048) { src = mk + (size_t)p * 9216; dst = g_pool6_k + (size_t)p * 36; }
    else { int q = p - 2048; src = mv + (size_t)q * 9216; dst = g_pool6_v + (size_t)q * 36; }
    __shared__ float rowsum[576];
    int tid = threadIdx.x;
    for (int task = tid; task < 576; task += 256) {
        int r = task / 6, j = task % 6;
        const float4* a = (const float4*)(src + r * 96 + j * 16);
        float4 v0 = a[0], v1 = a[1], v2 = a[2], v3 = a[3];
        rowsum[task] = (v0.x+v0.y+v0.z+v0.w) + (v1.x+v1.y+v1.z+v1.w)
                     + (v2.x+v2.y+v2.z+v2.w) + (v3.x+v3.y+v3.z+v3.w);
    }
    __syncthreads();
    if (tid < 36) {
        int by = tid / 6, bx = tid % 6;
        float s = 0.f;
        #pragma unroll
        for (int k = 0; k < 16; k++) s += rowsum[(by * 16 + k) * 6 + bx];
        dst[tid] = s * (1.0f / 256.0f);
    }
}

// ================= K2: per-(t,b,scale,pos) 1x1 conv + bias + relu =================
__global__ void k_conv(const float* __restrict__ kw, const float* __restrict__ kb,
                       const float* __restrict__ vw, const float* __restrict__ vb) {
    __shared__ float pooled[512];
    int bi = blockIdx.x;
    int kv = bi / 400;
    int rem = bi % 400;
    int tb = rem / 50;          // t*2 + b
    int task = rem % 50;
    int si, pos;
    if (task < 1)       { si = 0; pos = 0; }
    else if (task < 5)  { si = 1; pos = task - 1; }
    else if (task < 14) { si = 2; pos = task - 5; }
    else                { si = 3; pos = task - 14; }
    int s = c_scale[si];
    int g = 6 / s;
    int pi = pos / s, pj = pos % s;
    int C  = kv ? 512 : 256;
    int Co = kv ? 128 : 64;
    const float* p6 = kv ? g_pool6_v : g_pool6_k;
    int tid = threadIdx.x;
    float ginv = 1.0f / (float)(g * g);
    for (int c = tid; c < C; c += 256) {
        const float* pp = p6 + (size_t)(tb * C + c) * 36;
        float sum = 0.f;
        for (int a = 0; a < g; a++)
            for (int bb = 0; bb < g; bb++)
                sum += pp[(pi * g + a) * 6 + (pj * g + bb)];
        pooled[c] = sum * ginv;
    }
    __syncthreads();
    int t = tb >> 1;
    int L = 256 / Co;                 // lanes per output: 4 (keys) / 2 (values)
    int o = tid / L, r = tid % L;
    int chunk = C / L;
    const float* w = (kv ? vw : kw) + (size_t)((t * 4 + si) * Co + o) * C + r * chunk;
    const float* pl = pooled + r * chunk;
    float partial = 0.f;
    for (int i = 0; i < chunk; i += 4) {
        float4 wv = *(const float4*)(w + i);
        float4 pv = *(const float4*)(pl + i);
        partial += wv.x * pv.x + wv.y * pv.y + wv.z * pv.z + wv.w * pv.w;
    }
    for (int off = 1; off < L; off <<= 1)
        partial += __shfl_xor_sync(0xffffffffu, partial, off);
    if (r == 0) {
        float bias = (kv ? vb : kb)[(t * 4 + si) * Co + o];
        float v = fmaxf(partial + bias, 0.0f);
        float* cdst = (kv ? g_convv : g_convk) + (size_t)((tb * 4 + si) * Co + o) * 36 + pos;
        *cdst = v;
    }
}

// ================= K3: bilinear upsample to 6x6 + layout for attention =================
__global__ void k_upsample() {
    int idx = blockIdx.x * 256 + threadIdx.x;
    if (idx >= 221184) return;
    if (idx < 73728) {
        // keys -> g_mkT[b][c][m], fold Ck^-0.5 = 1/16
        int b = idx / (256 * 144);
        int rr = idx % (256 * 144);
        int c = rr / 144, m = rr % 144;
        int t = m / 36, pp = m % 36, i6 = pp / 6, j6 = pp % 6;
        int si = c >> 6, o = c & 63;
        int s = c_scale[si];
        const float* cv = g_convk + (size_t)(((t * 2 + b) * 4 + si) * 64 + o) * 36;
        int yi0 = UI0[si][i6], yi1 = UI1[si][i6]; float wy = UW[si][i6];
        int xi0 = UI0[si][j6], xi1 = UI1[si][j6]; float wx = UW[si][j6];
        float v00 = cv[yi0 * s + xi0], v01 = cv[yi0 * s + xi1];
        float v10 = cv[yi1 * s + xi0], v11 = cv[yi1 * s + xi1];
        float v = (1.f - wy) * ((1.f - wx) * v00 + wx * v01)
                +        wy  * ((1.f - wx) * v10 + wx * v11);
        g_mkT[(size_t)(b * 256 + c) * 144 + m] = v * 0.0625f;
    } else {
        int r0 = idx - 73728;
        int b = r0 / (144 * 512);
        int rr = r0 % (144 * 512);
        int m = rr / 512, vch = rr % 512;
        int t = m / 36, pp = m % 36, i6 = pp / 6, j6 = pp % 6;
        int si = vch >> 7, o = vch & 127;
        int s = c_scale[si];
        const float* cv = g_convv + (size_t)(((t * 2 + b) * 4 + si) * 128 + o) * 36;
        int yi0 = UI0[si][i6], yi1 = UI1[si][i6]; float wy = UW[si][i6];
        int xi0 = UI0[si][j6], xi1 = UI1[si][j6]; float wx = UW[si][j6];
        float v00 = cv[yi0 * s + xi0], v01 = cv[yi0 * s + xi1];
        float v10 = cv[yi1 * s + xi0], v11 = cv[yi1 * s + xi1];
        float v = (1.f - wy) * ((1.f - wx) * v00 + wx * v01)
                +        wy  * ((1.f - wx) * v10 + wx * v11);
        g_mvT[(size_t)(b * 144 + m) * 512 + vch] = v;
    }
}

// ================= K4: fused attention (QK -> softmax over M -> AV) + qv copy =================
// grid 144 = 2 b * 72 n-tiles of 128; block 256 threads.
// smem (floats): phase1: mkc[32*144]@0, qkc[32*128]@4608
//                later : att[144*128]@0, red[16*128]@18432, colmax@20480, colinv@20608,
//                        mvs[18*256]@20736   -> total 25344 floats = 101376 B
__global__ __launch_bounds__(256, 1)
void k_attn(const float* __restrict__ qk, const float* __restrict__ qv,
            float* __restrict__ out) {
    extern __shared__ float sm[];
    float* mkc    = sm;
    float* qkc    = sm + 4608;
    float* att    = sm;
    float* red    = sm + 18432;
    float* colmax = sm + 20480;
    float* colinv = sm + 20608;
    float* mvs    = sm + 20736;

    int tid = threadIdx.x;
    int b = blockIdx.x / 72, ntile = blockIdx.x % 72;
    int n0 = ntile * 128;
    int tm = tid >> 4, tn = tid & 15;       // 16 m-groups (9 m) x 16 n-groups (8 n)

    ull acc[9][4];
    #pragma unroll
    for (int i = 0; i < 9; i++)
        #pragma unroll
        for (int j = 0; j < 4; j++) acc[i][j] = 0ULL;

    const float* qkb = qk + (size_t)b * 256 * 9216 + n0;
    const float* mkb = g_mkT + (size_t)b * 256 * 144;

    // ---------- phase 1: scores[m][n] = sum_c mk[c][m]*qk[c][n] ----------
    for (int cc = 0; cc < 8; cc++) {
        __syncthreads();
        {   // mk chunk: 32 c x 144 m contiguous
            const float4* src = (const float4*)(mkb + cc * 32 * 144);
            for (int i = tid; i < 1152; i += 256) ((float4*)mkc)[i] = src[i];
        }
        {   // qk chunk: 32 rows x 128 cols
            for (int i = tid; i < 1024; i += 256) {
                int r = i >> 5, col = i & 31;
                ((float4*)qkc)[r * 32 + col] =
                    ((const float4*)(qkb + (size_t)(cc * 32 + r) * 9216))[col];
            }
        }
        {   // interleaved query_value copy (64 channels per chunk) — hides 75MB under compute
            const float* qvb = qv + (size_t)(b * 512 + cc * 64) * 9216 + n0;
            float* ob = out + (size_t)(b * 1024 + cc * 64) * 9216 + n0;
            for (int i = tid; i < 2048; i += 256) {
                int r = i >> 5, col = i & 31;
                ((float4*)(ob + (size_t)r * 9216))[col] =
                    ((const float4*)(qvb + (size_t)r * 9216))[col];
            }
        }
        __syncthreads();
        #pragma unroll 4
        for (int c = 0; c < 32; c++) {
            const float* mkrow = mkc + c * 144 + 9 * tm;
            const float* qrow  = qkc + c * 128 + 8 * tn;
            ull K[9], Q[4];
            #pragma unroll
            for (int i = 0; i < 9; i++) K[i] = dup2(mkrow[i]);
            #pragma unroll
            for (int j = 0; j < 4; j++) Q[j] = *(const ull*)(qrow + 2 * j);
            #pragma unroll
            for (int i = 0; i < 9; i++)
                #pragma unroll
                for (int j = 0; j < 4; j++)
                    acc[i][j] = fma2(K[i], Q[j], acc[i][j]);
        }
    }
    __syncthreads();   // done reading mkc/qkc before att overwrites that smem

    // ---------- softmax over m (per column n) ----------
    int nb = 8 * tn;
    #pragma unroll
    for (int j = 0; j < 4; j++) {
        float m0 = -1e30f, m1 = -1e30f;
        #pragma unroll
        for (int i = 0; i < 9; i++) {
            float lo, hi; unpack2(acc[i][j], lo, hi);
            m0 = fmaxf(m0, lo); m1 = fmaxf(m1, hi);
        }
        red[tm * 128 + nb + 2 * j]     = m0;
        red[tm * 128 + nb + 2 * j + 1] = m1;
    }
    __syncthreads();
    if (tid < 128) {
        float m = -1e30f;
        #pragma unroll
        for (int k = 0; k < 16; k++) m = fmaxf(m, red[k * 128 + tid]);
        colmax[tid] = m;
    }
    __syncthreads();
    #pragma unroll
    for (int j = 0; j < 4; j++) {
        float cm0 = colmax[nb + 2 * j], cm1 = colmax[nb + 2 * j + 1];
        float s0 = 0.f, s1 = 0.f;
        #pragma unroll
        for (int i = 0; i < 9; i++) {
            float lo, hi; unpack2(acc[i][j], lo, hi);
            lo = __expf(lo - cm0); hi = __expf(hi - cm1);
            s0 += lo; s1 += hi;
            acc[i][j] = pack2(lo, hi);
        }
        red[tm * 128 + nb + 2 * j]     = s0;
        red[tm * 128 + nb + 2 * j + 1] = s1;
    }
    __syncthreads();
    if (tid < 128) {
        float s = 0.f;
        #pragma unroll
        for (int k = 0; k < 16; k++) s += red[k * 128 + tid];
        colinv[tid] = 1.0f / s;
    }
    __syncthreads();
    #pragma unroll
    for (int j = 0; j < 4; j++) {
        float in0 = colinv[nb + 2 * j], in1 = colinv[nb + 2 * j + 1];
        #pragma unroll
        for (int i = 0; i < 9; i++) {
            float lo, hi; unpack2(acc[i][j], lo, hi);
            int m = 9 * tm + i;
            *(float2*)&att[m * 128 + nb + 2 * j] = make_float2(lo * in0, hi * in1);
        }
    }
    __syncthreads();

    // ---------- phase 2: mem[v][n] = sum_m mv[v][m]*att[m][n] ----------
    int tv = tid >> 3, tn2 = tid & 7;       // 32 v-groups (8 v) x 8 n-groups (16 n)
    const float* mvb = g_mvT + (size_t)b * 144 * 512;
    for (int vh = 0; vh < 2; vh++) {
        ull acc2[8][8];
        #pragma unroll
        for (int i = 0; i < 8; i++)
            #pragma unroll
            for (int j = 0; j < 8; j++) acc2[i][j] = 0ULL;
        for (int mc = 0; mc < 8; mc++) {
            __syncthreads();
            for (int i = tid; i < 1152; i += 256) {
                int r = i >> 6, col = i & 63;
                ((float4*)mvs)[r * 64 + col] =
                    ((const float4*)(mvb + (size_t)(mc * 18 + r) * 512 + vh * 256))[col];
            }
            __syncthreads();
            #pragma unroll 2
            for (int m = 0; m < 18; m++) {
                const float* arow = att + (mc * 18 + m) * 128 + 16 * tn2;
                ull A[8];
                #pragma unroll
                for (int q = 0; q < 4; q++) {
                    ulonglong2 t2 = *(const ulonglong2*)(arow + 4 * q);
                    A[2 * q] = t2.x; A[2 * q + 1] = t2.y;
                }
                const float* mrow = mvs + m * 256 + tv * 8;
                float4 f0 = *(const float4*)(mrow);
                float4 f1 = *(const float4*)(mrow + 4);
                ull MV[8];
                MV[0] = dup2(f0.x); MV[1] = dup2(f0.y); MV[2] = dup2(f0.z); MV[3] = dup2(f0.w);
                MV[4] = dup2(f1.x); MV[5] = dup2(f1.y); MV[6] = dup2(f1.z); MV[7] = dup2(f1.w);
                #pragma unroll
                for (int i = 0; i < 8; i++)
                    #pragma unroll
                    for (int j = 0; j < 8; j++)
                        acc2[i][j] = fma2(MV[i], A[j], acc2[i][j]);
            }
        }
        float* ob = out + (size_t)(b * 1024 + 512 + vh * 256 + tv * 8) * 9216 + n0 + 16 * tn2;
        #pragma unroll
        for (int i = 0; i < 8; i++) {
            ulonglong2* dst = (ulonglong2*)(ob + (size_t)i * 9216);
            dst[0] = make_ulonglong2(acc2[i][0], acc2[i][1]);
            dst[1] = make_ulonglong2(acc2[i][2], acc2[i][3]);
            dst[2] = make_ulonglong2(acc2[i][4], acc2[i][5]);
            dst[3] = make_ulonglong2(acc2[i][6], acc2[i][7]);
        }
    }
}

// ================= launch =================
extern "C" void kernel_launch(void* const* d_in, const int* in_sizes, int n_in,
                              void* d_out, int out_size) {
    const float* mk = (const float*)d_in[0];
    const float* mv = (const float*)d_in[1];
    const float* qk = (const float*)d_in[2];
    const float* qv = (const float*)d_in[3];
    const float* kw = (const float*)d_in[4];
    const float* kb = (const float*)d_in[5];
    const float* vw = (const float*)d_in[6];
    const float* vb = (const float*)d_in[7];
    float* out = (float*)d_out;

    k_pool<<<6144, 256>>>(mk, mv);
    k_conv<<<800, 256>>>(kw, kb, vw, vb);
    k_upsample<<<864, 256>>>();
    cudaFuncSetAttribute(k_attn, cudaFuncAttributeMaxDynamicSharedMemorySize, 101376);
    k_attn<<<144, 256, 101376>>>(qk, qv, out);
}

// round 4
// speedup vs baseline: 1.0283x; 1.0283x over previous
#include <cuda_runtime.h>
#include <cstdint>

typedef unsigned long long ull;

// ---------------- problem constants ----------------
// T=4, B=2, Ck=256, Cv=512, H=W=96, scales {1,2,3,6}, MAX=6, M=144, N=9216

// ---------------- device scratch (static, no allocation) ----------------
__device__ __align__(16) float g_pool6_k[2048 * 36];          // [T*B*Ck][36] block means
__device__ __align__(16) float g_pool6_v[4096 * 36];          // [T*B*Cv][36]
__device__ __align__(16) float g_convk[4 * 2 * 4 * 64 * 36];  // [tb][si][o][pos<=36]
__device__ __align__(16) float g_convv[4 * 2 * 4 * 128 * 36];
// duplicated layouts: every scalar stored twice (f32x2 broadcast operand, no dup movs)
__device__ __align__(16) float g_mkTd[2 * 256 * 288];         // [b][c][2*m] (x Ck^-0.5 folded)
__device__ __align__(16) float g_mvTd[2 * 144 * 1024];        // [b][m][2*v]

__constant__ int c_scale[4] = {1, 2, 3, 6};
// bilinear upsample tables (jax.image.resize bilinear, half-pixel == edge clamp here)
__constant__ int UI0[4][6] = {
    {0,0,0,0,0,0},
    {0,0,0,0,1,1},
    {0,0,0,1,1,2},
    {0,1,2,3,4,5}};
__constant__ int UI1[4][6] = {
    {0,0,0,0,0,0},
    {0,1,1,1,1,1},
    {0,1,1,2,2,2},
    {0,1,2,3,4,5}};
__constant__ float UW[4][6] = {
    {0.f,0.f,0.f,0.f,0.f,0.f},
    {0.f, 1.f/6.f, 0.5f, 5.f/6.f, 0.f, 0.f},
    {0.f, 0.25f, 0.75f, 0.25f, 0.75f, 0.f},
    {0.f,0.f,0.f,0.f,0.f,0.f}};

// ---------------- f32x2 helpers ----------------
__device__ __forceinline__ ull fma2(ull a, ull b, ull c) {
    ull d;
    asm("fma.rn.f32x2 %0, %1, %2, %3;" : "=l"(d) : "l"(a), "l"(b), "l"(c));
    return d;
}
__device__ __forceinline__ ull pack2(float lo, float hi) {
    ull d; unsigned a = __float_as_uint(lo), b = __float_as_uint(hi);
    asm("mov.b64 %0, {%1, %2};" : "=l"(d) : "r"(a), "r"(b));
    return d;
}
__device__ __forceinline__ void unpack2(ull v, float& lo, float& hi) {
    unsigned a, b;
    asm("mov.b64 {%0, %1}, %2;" : "=r"(a), "=r"(b) : "l"(v));
    lo = __uint_as_float(a); hi = __uint_as_float(b);
}

// ================= K1: 16x16 block means (all scales derive from these) =================
__global__ void k_pool(const float* __restrict__ mk, const float* __restrict__ mv) {
    int p = blockIdx.x;
    const float* src; float* dst;
    if (p < 2048) { src = mk + (size_t)p * 9216; dst = g_pool6_k + (size_t)p * 36; }
    else { int q = p - 2048; src = mv + (size_t)q * 9216; dst = g_pool6_v + (size_t)q * 36; }
    __shared__ float rowsum[576];
    int tid = threadIdx.x;
    for (int task = tid; task < 576; task += 256) {
        int r = task / 6, j = task % 6;
        const float4* a = (const float4*)(src + r * 96 + j * 16);
        float4 v0 = a[0], v1 = a[1], v2 = a[2], v3 = a[3];
        rowsum[task] = (v0.x+v0.y+v0.z+v0.w) + (v1.x+v1.y+v1.z+v1.w)
                     + (v2.x+v2.y+v2.z+v2.w) + (v3.x+v3.y+v3.z+v3.w);
    }
    __syncthreads();
    if (tid < 36) {
        int by = tid / 6, bx = tid % 6;
        float s = 0.f;
        #pragma unroll
        for (int k = 0; k < 16; k++) s += rowsum[(by * 16 + k) * 6 + bx];
        dst[tid] = s * (1.0f / 256.0f);
    }
}

// ================= K2: per-(t,b,scale,pos) 1x1 conv + bias + relu =================
__global__ void k_conv(const float* __restrict__ kw, const float* __restrict__ kb,
                       const float* __restrict__ vw, const float* __restrict__ vb) {
    __shared__ float pooled[512];
    int bi = blockIdx.x;
    int kv = bi / 400;
    int rem = bi % 400;
    int tb = rem / 50;          // t*2 + b
    int task = rem % 50;
    int si, pos;
    if (task < 1)       { si = 0; pos = 0; }
    else if (task < 5)  { si = 1; pos = task - 1; }
    else if (task < 14) { si = 2; pos = task - 5; }
    else                { si = 3; pos = task - 14; }
    int s = c_scale[si];
    int g = 6 / s;
    int pi = pos / s, pj = pos % s;
    int C  = kv ? 512 : 256;
    int Co = kv ? 128 : 64;
    const float* p6 = kv ? g_pool6_v : g_pool6_k;
    int tid = threadIdx.x;
    float ginv = 1.0f / (float)(g * g);
    for (int c = tid; c < C; c += 256) {
        const float* pp = p6 + (size_t)(tb * C + c) * 36;
        float sum = 0.f;
        for (int a = 0; a < g; a++)
            for (int bb = 0; bb < g; bb++)
                sum += pp[(pi * g + a) * 6 + (pj * g + bb)];
        pooled[c] = sum * ginv;
    }
    __syncthreads();
    int t = tb >> 1;
    int L = 256 / Co;                 // lanes per output: 4 (keys) / 2 (values)
    int o = tid / L, r = tid % L;
    int chunk = C / L;
    const float* w = (kv ? vw : kw) + (size_t)((t * 4 + si) * Co + o) * C + r * chunk;
    const float* pl = pooled + r * chunk;
    float partial = 0.f;
    for (int i = 0; i < chunk; i += 4) {
        float4 wv = *(const float4*)(w + i);
        float4 pv = *(const float4*)(pl + i);
        partial += wv.x * pv.x + wv.y * pv.y + wv.z * pv.z + wv.w * pv.w;
    }
    for (int off = 1; off < L; off <<= 1)
        partial += __shfl_xor_sync(0xffffffffu, partial, off);
    if (r == 0) {
        float bias = (kv ? vb : kb)[(t * 4 + si) * Co + o];
        float v = fmaxf(partial + bias, 0.0f);
        float* cdst = (kv ? g_convv : g_convk) + (size_t)((tb * 4 + si) * Co + o) * 36 + pos;
        *cdst = v;
    }
}

// ================= K3: bilinear upsample to 6x6 + duplicated attention layouts =================
__global__ void k_upsample() {
    int idx = blockIdx.x * 256 + threadIdx.x;
    if (idx >= 221184) return;
    if (idx < 73728) {
        // keys -> g_mkTd[b][c][2m], fold Ck^-0.5 = 1/16
        int b = idx / (256 * 144);
        int rr = idx % (256 * 144);
        int c = rr / 144, m = rr % 144;
        int t = m / 36, pp = m % 36, i6 = pp / 6, j6 = pp % 6;
        int si = c >> 6, o = c & 63;
        int s = c_scale[si];
        const float* cv = g_convk + (size_t)(((t * 2 + b) * 4 + si) * 64 + o) * 36;
        int yi0 = UI0[si][i6], yi1 = UI1[si][i6]; float wy = UW[si][i6];
        int xi0 = UI0[si][j6], xi1 = UI1[si][j6]; float wx = UW[si][j6];
        float v00 = cv[yi0 * s + xi0], v01 = cv[yi0 * s + xi1];
        float v10 = cv[yi1 * s + xi0], v11 = cv[yi1 * s + xi1];
        float v = (1.f - wy) * ((1.f - wx) * v00 + wx * v01)
                +        wy  * ((1.f - wx) * v10 + wx * v11);
        v *= 0.0625f;
        float* d = g_mkTd + (size_t)(b * 256 + c) * 288 + 2 * m;
        d[0] = v; d[1] = v;
    } else {
        int r0 = idx - 73728;
        int b = r0 / (144 * 512);
        int rr = r0 % (144 * 512);
        int m = rr / 512, vch = rr % 512;
        int t = m / 36, pp = m % 36, i6 = pp / 6, j6 = pp % 6;
        int si = vch >> 7, o = vch & 127;
        int s = c_scale[si];
        const float* cv = g_convv + (size_t)(((t * 2 + b) * 4 + si) * 128 + o) * 36;
        int yi0 = UI0[si][i6], yi1 = UI1[si][i6]; float wy = UW[si][i6];
        int xi0 = UI0[si][j6], xi1 = UI1[si][j6]; float wx = UW[si][j6];
        float v00 = cv[yi0 * s + xi0], v01 = cv[yi0 * s + xi1];
        float v10 = cv[yi1 * s + xi0], v11 = cv[yi1 * s + xi1];
        float v = (1.f - wy) * ((1.f - wx) * v00 + wx * v01)
                +        wy  * ((1.f - wx) * v10 + wx * v11);
        float* d = g_mvTd + (size_t)(b * 144 + m) * 1024 + 2 * vch;
        d[0] = v; d[1] = v;
    }
}

// ================= K4: fused attention (QK -> softmax over M -> AV) + qv copy =================
// grid 144 = 2 b * 72 n-tiles of 128; block 512 threads (16 warps/SM).
// smem (floats): phase1: mkc[32*288]@0, qkc[32*128]@9216      (13312 fl)
//                later : att[144*128]@0, red[16*128]@18432, colmax@20480, colinv@20608,
//                        mvs[18*512]@20736    -> total 29952 floats = 119808 B
__global__ __launch_bounds__(512, 1)
void k_attn(const float* __restrict__ qk, const float* __restrict__ qv,
            float* __restrict__ out) {
    extern __shared__ float sm[];
    float* mkc    = sm;
    float* qkc    = sm + 9216;
    float* att    = sm;
    float* red    = sm + 18432;
    float* colmax = sm + 20480;
    float* colinv = sm + 20608;
    float* mvs    = sm + 20736;

    int tid = threadIdx.x;
    int b = blockIdx.x / 72, ntile = blockIdx.x % 72;
    int n0 = ntile * 128;
    int tm = tid >> 5, tn = tid & 31;       // 16 m-groups (9 m) x 32 n-groups (4 n)

    ull acc[9][2];
    #pragma unroll
    for (int i = 0; i < 9; i++) { acc[i][0] = 0ULL; acc[i][1] = 0ULL; }

    const float* qkb = qk + (size_t)b * 256 * 9216 + n0;
    const float* mkb = g_mkTd + (size_t)b * 256 * 288;

    // ---------- phase 1: scores[m][n] = sum_c mk[c][m]*qk[c][n] ----------
    for (int cc = 0; cc < 8; cc++) {
        __syncthreads();
        {   // mk chunk (duplicated): 32 c x 288 contiguous floats
            const float4* src = (const float4*)(mkb + cc * 32 * 288);
            for (int i = tid; i < 2304; i += 512) ((float4*)mkc)[i] = src[i];
        }
        {   // qk chunk: 32 rows x 128 cols
            for (int i = tid; i < 1024; i += 512) {
                int r = i >> 5, col = i & 31;
                ((float4*)qkc)[r * 32 + col] =
                    ((const float4*)(qkb + (size_t)(cc * 32 + r) * 9216))[col];
            }
        }
        {   // interleaved query_value copy (64 channels per chunk) — hidden under compute
            const float* qvb = qv + (size_t)(b * 512 + cc * 64) * 9216 + n0;
            float* ob = out + (size_t)(b * 1024 + cc * 64) * 9216 + n0;
            for (int i = tid; i < 2048; i += 512) {
                int r = i >> 5, col = i & 31;
                ((float4*)(ob + (size_t)r * 9216))[col] =
                    ((const float4*)(qvb + (size_t)r * 9216))[col];
            }
        }
        __syncthreads();
        #pragma unroll 8
        for (int c = 0; c < 32; c++) {
            const float* krow = mkc + c * 288 + 18 * tm;   // duplicated pairs
            const float* qrow = qkc + c * 128 + 4 * tn;
            ulonglong2 q2 = *(const ulonglong2*)qrow;      // 4 n-cols = 2 f32x2
            ull K[9];
            #pragma unroll
            for (int i = 0; i < 9; i++) K[i] = *(const ull*)(krow + 2 * i);
            #pragma unroll
            for (int i = 0; i < 9; i++) {
                acc[i][0] = fma2(K[i], q2.x, acc[i][0]);
                acc[i][1] = fma2(K[i], q2.y, acc[i][1]);
            }
        }
    }
    __syncthreads();   // done reading mkc/qkc before att overwrites that smem

    // ---------- softmax over m (per column n) ----------
    int nb = 4 * tn;
    #pragma unroll
    for (int j = 0; j < 2; j++) {
        float m0 = -1e30f, m1 = -1e30f;
        #pragma unroll
        for (int i = 0; i < 9; i++) {
            float lo, hi; unpack2(acc[i][j], lo, hi);
            m0 = fmaxf(m0, lo); m1 = fmaxf(m1, hi);
        }
        red[tm * 128 + nb + 2 * j]     = m0;
        red[tm * 128 + nb + 2 * j + 1] = m1;
    }
    __syncthreads();
    if (tid < 128) {
        float m = -1e30f;
        #pragma unroll
        for (int k = 0; k < 16; k++) m = fmaxf(m, red[k * 128 + tid]);
        colmax[tid] = m;
    }
    __syncthreads();
    #pragma unroll
    for (int j = 0; j < 2; j++) {
        float cm0 = colmax[nb + 2 * j], cm1 = colmax[nb + 2 * j + 1];
        float s0 = 0.f, s1 = 0.f;
        #pragma unroll
        for (int i = 0; i < 9; i++) {
            float lo, hi; unpack2(acc[i][j], lo, hi);
            lo = __expf(lo - cm0); hi = __expf(hi - cm1);
            s0 += lo; s1 += hi;
            acc[i][j] = pack2(lo, hi);
        }
        red[tm * 128 + nb + 2 * j]     = s0;
        red[tm * 128 + nb + 2 * j + 1] = s1;
    }
    __syncthreads();
    if (tid < 128) {
        float s = 0.f;
        #pragma unroll
        for (int k = 0; k < 16; k++) s += red[k * 128 + tid];
        colinv[tid] = 1.0f / s;
    }
    __syncthreads();
    #pragma unroll
    for (int j = 0; j < 2; j++) {
        float in0 = colinv[nb + 2 * j], in1 = colinv[nb + 2 * j + 1];
        #pragma unroll
        for (int i = 0; i < 9; i++) {
            float lo, hi; unpack2(acc[i][j], lo, hi);
            int m = 9 * tm + i;
            *(float2*)&att[m * 128 + nb + 2 * j] = make_float2(lo * in0, hi * in1);
        }
    }
    __syncthreads();

    // ---------- phase 2: mem[v][n] = sum_m mv[v][m]*att[m][n] ----------
    int tv = tid >> 4, tn2 = tid & 15;      // 32 v-groups (8 v) x 16 n-groups (8 n)
    const float* mvb = g_mvTd + (size_t)b * 144 * 1024;
    for (int vh = 0; vh < 2; vh++) {
        ull acc2[8][4];
        #pragma unroll
        for (int i = 0; i < 8; i++)
            #pragma unroll
            for (int j = 0; j < 4; j++) acc2[i][j] = 0ULL;
        for (int mc = 0; mc < 8; mc++) {
            __syncthreads();
            // mv chunk (duplicated): 18 m rows x 512 floats (v half vh)
            for (int i = tid; i < 2304; i += 512) {
                int r = i >> 7, col = i & 127;
                ((float4*)mvs)[r * 128 + col] =
                    ((const float4*)(mvb + (size_t)(mc * 18 + r) * 1024 + vh * 512))[col];
            }
            __syncthreads();
            #pragma unroll 6
            for (int m = 0; m < 18; m++) {
                const float* arow = att + (mc * 18 + m) * 128 + 8 * tn2;
                ulonglong2 a01 = ((const ulonglong2*)arow)[0];
                ulonglong2 a23 = ((const ulonglong2*)arow)[1];
                const float* mrow = mvs + m * 512 + 16 * tv;   // duplicated pairs
                ull MV[8];
                #pragma unroll
                for (int i = 0; i < 8; i++) MV[i] = *(const ull*)(mrow + 2 * i);
                #pragma unroll
                for (int i = 0; i < 8; i++) {
                    acc2[i][0] = fma2(MV[i], a01.x, acc2[i][0]);
                    acc2[i][1] = fma2(MV[i], a01.y, acc2[i][1]);
                    acc2[i][2] = fma2(MV[i], a23.x, acc2[i][2]);
                    acc2[i][3] = fma2(MV[i], a23.y, acc2[i][3]);
                }
            }
        }
        float* ob = out + (size_t)(b * 1024 + 512 + vh * 256 + tv * 8) * 9216 + n0 + 8 * tn2;
        #pragma unroll
        for (int i = 0; i < 8; i++) {
            ulonglong2* dst = (ulonglong2*)(ob + (size_t)i * 9216);
            dst[0] = make_ulonglong2(acc2[i][0], acc2[i][1]);
            dst[1] = make_ulonglong2(acc2[i][2], acc2[i][3]);
        }
    }
}

// ================= launch =================
extern "C" void kernel_launch(void* const* d_in, const int* in_sizes, int n_in,
                              void* d_out, int out_size) {
    const float* mk = (const float*)d_in[0];
    const float* mv = (const float*)d_in[1];
    const float* qk = (const float*)d_in[2];
    const float* qv = (const float*)d_in[3];
    const float* kw = (const float*)d_in[4];
    const float* kb = (const float*)d_in[5];
    const float* vw = (const float*)d_in[6];
    const float* vb = (const float*)d_in[7];
    float* out = (float*)d_out;

    k_pool<<<6144, 256>>>(mk, mv);
    k_conv<<<800, 256>>>(kw, kb, vw, vb);
    k_upsample<<<864, 256>>>();
    cudaFuncSetAttribute(k_attn, cudaFuncAttributeMaxDynamicSharedMemorySize, 119808);
    k_attn<<<144, 512, 119808>>>(qk, qv, out);
}

// round 5
// speedup vs baseline: 1.0664x; 1.0371x over previous
#include <cuda_runtime.h>
#include <cstdint>

typedef unsigned long long ull;

// ---------------- problem constants ----------------
// T=4, B=2, Ck=256, Cv=512, H=W=96, scales {1,2,3,6}, MAX=6, M=144, N=9216

// ---------------- device scratch (static, no allocation) ----------------
__device__ __align__(16) float g_pool6_k[2048 * 36];          // [T*B*Ck][36] block means
__device__ __align__(16) float g_pool6_v[4096 * 36];          // [T*B*Cv][36]
__device__ __align__(16) float g_convk[4 * 2 * 4 * 64 * 36];  // [tb][si][o][pos<=36]
__device__ __align__(16) float g_convv[4 * 2 * 4 * 128 * 36];
// duplicated layouts: every scalar stored twice (f32x2 broadcast operand, no dup movs)
__device__ __align__(16) float g_mkTd[2 * 256 * 288];         // [b][c][2*m] (x Ck^-0.5 folded)
__device__ __align__(16) float g_mvTd[2 * 144 * 1024];        // [b][m][2*v]

__constant__ int c_scale[4] = {1, 2, 3, 6};
// bilinear upsample tables (jax.image.resize bilinear, half-pixel == edge clamp here)
__constant__ int UI0[4][6] = {
    {0,0,0,0,0,0},
    {0,0,0,0,1,1},
    {0,0,0,1,1,2},
    {0,1,2,3,4,5}};
__constant__ int UI1[4][6] = {
    {0,0,0,0,0,0},
    {0,1,1,1,1,1},
    {0,1,1,2,2,2},
    {0,1,2,3,4,5}};
__constant__ float UW[4][6] = {
    {0.f,0.f,0.f,0.f,0.f,0.f},
    {0.f, 1.f/6.f, 0.5f, 5.f/6.f, 0.f, 0.f},
    {0.f, 0.25f, 0.75f, 0.25f, 0.75f, 0.f},
    {0.f,0.f,0.f,0.f,0.f,0.f}};

// ---------------- f32x2 helpers ----------------
__device__ __forceinline__ ull fma2(ull a, ull b, ull c) {
    ull d;
    asm("fma.rn.f32x2 %0, %1, %2, %3;" : "=l"(d) : "l"(a), "l"(b), "l"(c));
    return d;
}
__device__ __forceinline__ ull pack2(float lo, float hi) {
    ull d; unsigned a = __float_as_uint(lo), b = __float_as_uint(hi);
    asm("mov.b64 %0, {%1, %2};" : "=l"(d) : "r"(a), "r"(b));
    return d;
}
__device__ __forceinline__ void unpack2(ull v, float& lo, float& hi) {
    unsigned a, b;
    asm("mov.b64 {%0, %1}, %2;" : "=r"(a), "=r"(b) : "l"(v));
    lo = __uint_as_float(a); hi = __uint_as_float(b);
}

// ================= K1: 16x16 block means (all scales derive from these) =================
__global__ void k_pool(const float* __restrict__ mk, const float* __restrict__ mv) {
    int p = blockIdx.x;
    const float* src; float* dst;
    if (p < 2048) { src = mk + (size_t)p * 9216; dst = g_pool6_k + (size_t)p * 36; }
    else { int q = p - 2048; src = mv + (size_t)q * 9216; dst = g_pool6_v + (size_t)q * 36; }
    __shared__ float rowsum[576];
    int tid = threadIdx.x;
    for (int task = tid; task < 576; task += 256) {
        int r = task / 6, j = task % 6;
        const float4* a = (const float4*)(src + r * 96 + j * 16);
        float4 v0 = a[0], v1 = a[1], v2 = a[2], v3 = a[3];
        rowsum[task] = (v0.x+v0.y+v0.z+v0.w) + (v1.x+v1.y+v1.z+v1.w)
                     + (v2.x+v2.y+v2.z+v2.w) + (v3.x+v3.y+v3.z+v3.w);
    }
    __syncthreads();
    if (tid < 36) {
        int by = tid / 6, bx = tid % 6;
        float s = 0.f;
        #pragma unroll
        for (int k = 0; k < 16; k++) s += rowsum[(by * 16 + k) * 6 + bx];
        dst[tid] = s * (1.0f / 256.0f);
    }
}

// ================= K2: per-(t,b,scale,pos) 1x1 conv + bias + relu =================
__global__ void k_conv(const float* __restrict__ kw, const float* __restrict__ kb,
                       const float* __restrict__ vw, const float* __restrict__ vb) {
    __shared__ float pooled[512];
    int bi = blockIdx.x;
    int kv = bi / 400;
    int rem = bi % 400;
    int tb = rem / 50;          // t*2 + b
    int task = rem % 50;
    int si, pos;
    if (task < 1)       { si = 0; pos = 0; }
    else if (task < 5)  { si = 1; pos = task - 1; }
    else if (task < 14) { si = 2; pos = task - 5; }
    else                { si = 3; pos = task - 14; }
    int s = c_scale[si];
    int g = 6 / s;
    int pi = pos / s, pj = pos % s;
    int C  = kv ? 512 : 256;
    int Co = kv ? 128 : 64;
    const float* p6 = kv ? g_pool6_v : g_pool6_k;
    int tid = threadIdx.x;
    float ginv = 1.0f / (float)(g * g);
    for (int c = tid; c < C; c += 256) {
        const float* pp = p6 + (size_t)(tb * C + c) * 36;
        float sum = 0.f;
        for (int a = 0; a < g; a++)
            for (int bb = 0; bb < g; bb++)
                sum += pp[(pi * g + a) * 6 + (pj * g + bb)];
        pooled[c] = sum * ginv;
    }
    __syncthreads();
    int t = tb >> 1;
    int L = 256 / Co;                 // lanes per output: 4 (keys) / 2 (values)
    int o = tid / L, r = tid % L;
    int chunk = C / L;
    const float* w = (kv ? vw : kw) + (size_t)((t * 4 + si) * Co + o) * C + r * chunk;
    const float* pl = pooled + r * chunk;
    float partial = 0.f;
    for (int i = 0; i < chunk; i += 4) {
        float4 wv = *(const float4*)(w + i);
        float4 pv = *(const float4*)(pl + i);
        partial += wv.x * pv.x + wv.y * pv.y + wv.z * pv.z + wv.w * pv.w;
    }
    for (int off = 1; off < L; off <<= 1)
        partial += __shfl_xor_sync(0xffffffffu, partial, off);
    if (r == 0) {
        float bias = (kv ? vb : kb)[(t * 4 + si) * Co + o];
        float v = fmaxf(partial + bias, 0.0f);
        float* cdst = (kv ? g_convv : g_convk) + (size_t)((tb * 4 + si) * Co + o) * 36 + pos;
        *cdst = v;
    }
}

// ================= K3: bilinear upsample to 6x6 + duplicated attention layouts =================
__global__ void k_upsample() {
    int idx = blockIdx.x * 256 + threadIdx.x;
    if (idx >= 221184) return;
    if (idx < 73728) {
        // keys -> g_mkTd[b][c][2m], fold Ck^-0.5 = 1/16
        int b = idx / (256 * 144);
        int rr = idx % (256 * 144);
        int c = rr / 144, m = rr % 144;
        int t = m / 36, pp = m % 36, i6 = pp / 6, j6 = pp % 6;
        int si = c >> 6, o = c & 63;
        int s = c_scale[si];
        const float* cv = g_convk + (size_t)(((t * 2 + b) * 4 + si) * 64 + o) * 36;
        int yi0 = UI0[si][i6], yi1 = UI1[si][i6]; float wy = UW[si][i6];
        int xi0 = UI0[si][j6], xi1 = UI1[si][j6]; float wx = UW[si][j6];
        float v00 = cv[yi0 * s + xi0], v01 = cv[yi0 * s + xi1];
        float v10 = cv[yi1 * s + xi0], v11 = cv[yi1 * s + xi1];
        float v = (1.f - wy) * ((1.f - wx) * v00 + wx * v01)
                +        wy  * ((1.f - wx) * v10 + wx * v11);
        v *= 0.0625f;
        float* d = g_mkTd + (size_t)(b * 256 + c) * 288 + 2 * m;
        d[0] = v; d[1] = v;
    } else {
        int r0 = idx - 73728;
        int b = r0 / (144 * 512);
        int rr = r0 % (144 * 512);
        int m = rr / 512, vch = rr % 512;
        int t = m / 36, pp = m % 36, i6 = pp / 6, j6 = pp % 6;
        int si = vch >> 7, o = vch & 127;
        int s = c_scale[si];
        const float* cv = g_convv + (size_t)(((t * 2 + b) * 4 + si) * 128 + o) * 36;
        int yi0 = UI0[si][i6], yi1 = UI1[si][i6]; float wy = UW[si][i6];
        int xi0 = UI0[si][j6], xi1 = UI1[si][j6]; float wx = UW[si][j6];
        float v00 = cv[yi0 * s + xi0], v01 = cv[yi0 * s + xi1];
        float v10 = cv[yi1 * s + xi0], v11 = cv[yi1 * s + xi1];
        float v = (1.f - wy) * ((1.f - wx) * v00 + wx * v01)
                +        wy  * ((1.f - wx) * v10 + wx * v11);
        float* d = g_mvTd + (size_t)(b * 144 + m) * 1024 + 2 * vch;
        d[0] = v; d[1] = v;
    }
}

// ================= K4: fused attention (QK -> softmax over M -> AV) + qv copy =================
// grid 144 = 2 b * 72 n-tiles of 128; block 512 threads (16 warps/SM).
// smem (floats): phase1: mkc[32*288]@0, qkc[32*128]@9216      (13312 fl)
//                later : att[144*128]@0, red[16*128]@18432, colmax@20480, colinv@20608,
//                        mvs[18*512]@20736    -> total 29952 floats = 119808 B
__global__ __launch_bounds__(512, 1)
void k_attn(const float* __restrict__ qk, const float* __restrict__ qv,
            float* __restrict__ out) {
    extern __shared__ float sm[];
    float* mkc    = sm;
    float* qkc    = sm + 9216;
    float* att    = sm;
    float* red    = sm + 18432;
    float* colmax = sm + 20480;
    float* colinv = sm + 20608;
    float* mvs    = sm + 20736;

    int tid = threadIdx.x;
    int b = blockIdx.x / 72, ntile = blockIdx.x % 72;
    int n0 = ntile * 128;
    int tm = tid >> 5, tn = tid & 31;       // 16 m-groups (9 m) x 32 n-groups (4 n)

    ull acc[9][2];
    #pragma unroll
    for (int i = 0; i < 9; i++) { acc[i][0] = 0ULL; acc[i][1] = 0ULL; }

    const float* qkb = qk + (size_t)b * 256 * 9216 + n0;
    const float* mkb = g_mkTd + (size_t)b * 256 * 288;

    // ---------- phase 1: scores[m][n] = sum_c mk[c][m]*qk[c][n] ----------
    for (int cc = 0; cc < 8; cc++) {
        __syncthreads();
        {   // mk chunk (duplicated): 32 c x 288 contiguous floats
            const float4* src = (const float4*)(mkb + cc * 32 * 288);
            for (int i = tid; i < 2304; i += 512) ((float4*)mkc)[i] = src[i];
        }
        {   // qk chunk: 32 rows x 128 cols
            for (int i = tid; i < 1024; i += 512) {
                int r = i >> 5, col = i & 31;
                ((float4*)qkc)[r * 32 + col] =
                    ((const float4*)(qkb + (size_t)(cc * 32 + r) * 9216))[col];
            }
        }
        {   // interleaved query_value copy (64 channels per chunk) — hidden under compute
            const float* qvb = qv + (size_t)(b * 512 + cc * 64) * 9216 + n0;
            float* ob = out + (size_t)(b * 1024 + cc * 64) * 9216 + n0;
            for (int i = tid; i < 2048; i += 512) {
                int r = i >> 5, col = i & 31;
                ((float4*)(ob + (size_t)r * 9216))[col] =
                    ((const float4*)(qvb + (size_t)r * 9216))[col];
            }
        }
        __syncthreads();
        #pragma unroll 8
        for (int c = 0; c < 32; c++) {
            const float* krow = mkc + c * 288 + 18 * tm;   // duplicated pairs
            const float* qrow = qkc + c * 128 + 4 * tn;
            ulonglong2 q2 = *(const ulonglong2*)qrow;      // 4 n-cols = 2 f32x2
            ull K[9];
            #pragma unroll
            for (int i = 0; i < 9; i++) K[i] = *(const ull*)(krow + 2 * i);
            #pragma unroll
            for (int i = 0; i < 9; i++) {
                acc[i][0] = fma2(K[i], q2.x, acc[i][0]);
                acc[i][1] = fma2(K[i], q2.y, acc[i][1]);
            }
        }
    }
    __syncthreads();   // done reading mkc/qkc before att overwrites that smem

    // ---------- softmax over m (per column n) ----------
    int nb = 4 * tn;
    #pragma unroll
    for (int j = 0; j < 2; j++) {
        float m0 = -1e30f, m1 = -1e30f;
        #pragma unroll
        for (int i = 0; i < 9; i++) {
            float lo, hi; unpack2(acc[i][j], lo, hi);
            m0 = fmaxf(m0, lo); m1 = fmaxf(m1, hi);
        }
        red[tm * 128 + nb + 2 * j]     = m0;
        red[tm * 128 + nb + 2 * j + 1] = m1;
    }
    __syncthreads();
    if (tid < 128) {
        float m = -1e30f;
        #pragma unroll
        for (int k = 0; k < 16; k++) m = fmaxf(m, red[k * 128 + tid]);
        colmax[tid] = m;
    }
    __syncthreads();
    #pragma unroll
    for (int j = 0; j < 2; j++) {
        float cm0 = colmax[nb + 2 * j], cm1 = colmax[nb + 2 * j + 1];
        float s0 = 0.f, s1 = 0.f;
        #pragma unroll
        for (int i = 0; i < 9; i++) {
            float lo, hi; unpack2(acc[i][j], lo, hi);
            lo = __expf(lo - cm0); hi = __expf(hi - cm1);
            s0 += lo; s1 += hi;
            acc[i][j] = pack2(lo, hi);
        }
        red[tm * 128 + nb + 2 * j]     = s0;
        red[tm * 128 + nb + 2 * j + 1] = s1;
    }
    __syncthreads();
    if (tid < 128) {
        float s = 0.f;
        #pragma unroll
        for (int k = 0; k < 16; k++) s += red[k * 128 + tid];
        colinv[tid] = 1.0f / s;
    }
    __syncthreads();
    #pragma unroll
    for (int j = 0; j < 2; j++) {
        float in0 = colinv[nb + 2 * j], in1 = colinv[nb + 2 * j + 1];
        #pragma unroll
        for (int i = 0; i < 9; i++) {
            float lo, hi; unpack2(acc[i][j], lo, hi);
            int m = 9 * tm + i;
            *(float2*)&att[m * 128 + nb + 2 * j] = make_float2(lo * in0, hi * in1);
        }
    }
    __syncthreads();

    // ---------- phase 2: mem[v][n] = sum_m mv[v][m]*att[m][n] ----------
    int tv = tid >> 4, tn2 = tid & 15;      // 32 v-groups (8 v) x 16 n-groups (8 n)
    const float* mvb = g_mvTd + (size_t)b * 144 * 1024;
    for (int vh = 0; vh < 2; vh++) {
        ull acc2[8][4];
        #pragma unroll
        for (int i = 0; i < 8; i++)
            #pragma unroll
            for (int j = 0; j < 4; j++) acc2[i][j] = 0ULL;
        for (int mc = 0; mc < 8; mc++) {
            __syncthreads();
            // mv chunk (duplicated): 18 m rows x 512 floats (v half vh)
            for (int i = tid; i < 2304; i += 512) {
                int r = i >> 7, col = i & 127;
                ((float4*)mvs)[r * 128 + col] =
                    ((const float4*)(mvb + (size_t)(mc * 18 + r) * 1024 + vh * 512))[col];
            }
            __syncthreads();
            #pragma unroll 6
            for (int m = 0; m < 18; m++) {
                const float* arow = att + (mc * 18 + m) * 128 + 8 * tn2;
                ulonglong2 a01 = ((const ulonglong2*)arow)[0];
                ulonglong2 a23 = ((const ulonglong2*)arow)[1];
                const float* mrow = mvs + m * 512 + 16 * tv;   // duplicated pairs
                ull MV[8];
                #pragma unroll
                for (int i = 0; i < 8; i++) MV[i] = *(const ull*)(mrow + 2 * i);
                #pragma unroll
                for (int i = 0; i < 8; i++) {
                    acc2[i][0] = fma2(MV[i], a01.x, acc2[i][0]);
                    acc2[i][1] = fma2(MV[i], a01.y, acc2[i][1]);
                    acc2[i][2] = fma2(MV[i], a23.x, acc2[i][2]);
                    acc2[i][3] = fma2(MV[i], a23.y, acc2[i][3]);
                }
            }
        }
        float* ob = out + (size_t)(b * 1024 + 512 + vh * 256 + tv * 8) * 9216 + n0 + 8 * tn2;
        #pragma unroll
        for (int i = 0; i < 8; i++) {
            ulonglong2* dst = (ulonglong2*)(ob + (size_t)i * 9216);
            dst[0] = make_ulonglong2(acc2[i][0], acc2[i][1]);
            dst[1] = make_ulonglong2(acc2[i][2], acc2[i][3]);
        }
    }
}

// ================= launch =================
extern "C" void kernel_launch(void* const* d_in, const int* in_sizes, int n_in,
                              void* d_out, int out_size) {
    const float* mk = (const float*)d_in[0];
    const float* mv = (const float*)d_in[1];
    const float* qk = (const float*)d_in[2];
    const float* qv = (const float*)d_in[3];
    const float* kw = (const float*)d_in[4];
    const float* kb = (const float*)d_in[5];
    const float* vw = (const float*)d_in[6];
    const float* vb = (const float*)d_in[7];
    float* out = (float*)d_out;

    k_pool<<<6144, 256>>>(mk, mv);
    k_conv<<<800, 256>>>(kw, kb, vw, vb);
    k_upsample<<<864, 256>>>();
    cudaFuncSetAttribute(k_attn, cudaFuncAttributeMaxDynamicSharedMemorySize, 119808);
    k_attn<<<144, 512, 119808>>>(qk, qv, out);
}